// round 11
// baseline (speedup 1.0000x reference)
#include <cuda_runtime.h>

#define B_DIM 16
#define G_DIM 1708
#define GV4   (G_DIM / 4)        // 427 <= active threads: one float4 group per thread
#define H_DIM 5
#define NC 16                    // Taylor n = 0..15; 4.5^16/16!/e^4.5 ~ 1.5e-5 at guard
#define GUARD 4.5f
#define NTHREADS 448
#define NWARPS 14
#define ZCHUNK ((GV4 + H_DIM - 1) / H_DIM)   // 86 float4 groups zeroed per CTA

// Replay-safe zero-completion counter (monotone; graph executions sequential).
__device__ unsigned g_zero[B_DIM];

__constant__ float c_invfact[NC] = {
    1.0f, 1.0f, 0.5f,
    1.6666666666666666e-01f, 4.1666666666666664e-02f, 8.3333333333333332e-03f,
    1.3888888888888889e-03f, 1.9841269841269841e-04f, 2.4801587301587302e-05f,
    2.7557319223985893e-06f, 2.7557319223985894e-07f, 2.5052108385441720e-08f,
    2.0876756987868100e-09f, 1.6059043836821616e-10f, 1.1470745597729726e-11f,
    7.6471637318198174e-13f };

// Exact fallback; never taken on this data. Shift m = |u|*kam >= max_j(u*k_j)
// is overflow-safe and cancels in the num/den ratio.
__device__ __noinline__ float exact_row(float u, const float* __restrict__ xb,
                                        const float* __restrict__ wkh,
                                        const float* __restrict__ wvh,
                                        float kam, float ki, float vi) {
    const float m = fabsf(u) * kam;
    float s1 = 0.f, s2 = 0.f;
    for (int j = 0; j < G_DIM; j++) {
        const float xj = xb[j];
        const float kj = xj * wkh[j];
        const float vj = xj * wvh[j];
        const float e  = __expf(fmaf(u, kj, -m));
        s1 += e;
        s2 = fmaf(e, vj, s2);
    }
    const float eii = __expf(fmaf(u, ki, -m));
    return (s2 - eii * vi) / s1;
}

// Shrinking butterfly round: N outputs from 2N inputs across stride S.
// Lane keeps the half whose value-bit matches its own lane-bit S.
template<int S, int N>
__device__ __forceinline__ void red_round(const float* __restrict__ in,
                                          float* __restrict__ outv, int lane) {
    const bool up = (lane & S) != 0;
#pragma unroll
    for (int j = 0; j < N; j++) {
        const float send = up ? in[j] : in[j + N];
        const float recv = __shfl_xor_sync(0xffffffffu, send, S);
        outv[j] = (up ? in[j + N] : in[j]) + recv;
    }
}

// One CTA per (b,h). Entry: zero 1/5 of out[b,:], fence, bump g_zero[b]
// (early release). Exit: spin for all 5 zero-bumps (late acquire — counter is
// long since satisfied), then atomicAdd contributions. No memset node needed.
// den(u) = sum_n (S_n/n!) u^n,  num(u) = sum_n (M_n/n!) u^n
// out[b,i] = sum_h W0[h] * (num_h(q_i) - exp(q_i*k_i)*v_i) / den_h(q_i)
__global__ __launch_bounds__(NTHREADS, 1)
void attn_head_red_kernel(const float* __restrict__ x,  const float* __restrict__ WQ,
                          const float* __restrict__ WK, const float* __restrict__ WV,
                          const float* __restrict__ W0, float* __restrict__ out) {
    const int b = blockIdx.x;
    const int h = blockIdx.y;
    const int tid = threadIdx.x;
    const int wid = tid >> 5, lane = tid & 31;
    const bool act = (tid < GV4);

    __shared__ float wR[NWARPS][32];        // per-warp reduced (S0..15, M0..15)
    __shared__ float cS[NC], cM[NC];
    __shared__ float wkam[NWARPS];
    __shared__ float s_kam;
    __shared__ unsigned s_target;

    const float4* __restrict__ xb4 = (const float4*)(x  + b * G_DIM);
    const float4* __restrict__ wq4 = (const float4*)(WQ + h * G_DIM);
    const float4* __restrict__ wk4 = (const float4*)(WK + h * G_DIM);
    const float4* __restrict__ wv4 = (const float4*)(WV + h * G_DIM);
    float* __restrict__ ob = out + b * G_DIM;
    float4* __restrict__ ob4 = (float4*)ob;

    // ---- Load everything this thread will ever need (one DRAM round-trip).
    float4 xv = make_float4(0.f, 0.f, 0.f, 0.f), qw = xv, kw = xv, vw = xv;
    if (act) {
        xv = xb4[tid];
        qw = wq4[tid];   // prefetched: latency hides under moments+reduction
        kw = wk4[tid];
        vw = wv4[tid];
    }

    // ---- Zero this CTA's 1/5 slice of out[b,:]; release early.
    {
        const int zg = h * ZCHUNK + tid;
        if (tid < ZCHUNK && zg < GV4)
            ob4[zg] = make_float4(0.f, 0.f, 0.f, 0.f);
    }
    __threadfence();                 // publish ~86 zero-stores (cheap: few in flight)
    __syncthreads();
    if (tid == 0) {
        const unsigned t = atomicAdd(&g_zero[b], 1u);
        s_target = (t / H_DIM) * H_DIM + H_DIM;   // all 5 CTAs of this execution agree
    }

    const float k0 = xv.x * kw.x, v0 = xv.x * vw.x;
    const float k1 = xv.y * kw.y, v1 = xv.y * vw.y;
    const float k2 = xv.z * kw.z, v2 = xv.z * vw.z;
    const float k3 = xv.w * kw.w, v3 = xv.w * vw.w;

    float kam = fmaxf(fmaxf(fabsf(k0), fabsf(k1)), fmaxf(fabsf(k2), fabsf(k3)));

    // ---- Moments: R[0..15] = S_n partials, R[16..31] = M_n partials.
    float R[32];
#pragma unroll
    for (int n = 0; n < 32; n++) R[n] = 0.f;
    if (act) {
#pragma unroll
        for (int e = 0; e < 4; e++) {
            const float k = (e == 0) ? k0 : (e == 1) ? k1 : (e == 2) ? k2 : k3;
            const float v = (e == 0) ? v0 : (e == 1) ? v1 : (e == 2) ? v2 : v3;
            const float ksq = k * k;
            const float kq  = ksq * ksq;
            float p0 = 1.f, p1 = k, p2 = ksq, p3 = ksq * k;
#pragma unroll
            for (int n = 0; n < NC; n += 4) {
                R[n + 0]      += p0;  R[NC + n + 0] = fmaf(p0, v, R[NC + n + 0]);
                R[n + 1]      += p1;  R[NC + n + 1] = fmaf(p1, v, R[NC + n + 1]);
                R[n + 2]      += p2;  R[NC + n + 2] = fmaf(p2, v, R[NC + n + 2]);
                R[n + 3]      += p3;  R[NC + n + 3] = fmaf(p3, v, R[NC + n + 3]);
                p0 *= kq; p1 *= kq; p2 *= kq; p3 *= kq;
            }
        }
    }

    // ---- Shrinking-butterfly warp reduce: 31 shuffle-pairs total.
    // After 5 rounds, lane l holds the warp-sum of value index l.
    float L16[16], L8[8], L4[4], L2[2], L1[1];
    red_round<16, 16>(R,   L16, lane);
    red_round< 8,  8>(L16, L8,  lane);
    red_round< 4,  4>(L8,  L4,  lane);
    red_round< 2,  2>(L4,  L2,  lane);
    red_round< 1,  1>(L2,  L1,  lane);
    wR[wid][lane] = L1[0];

#pragma unroll
    for (int o = 16; o > 0; o >>= 1)
        kam = fmaxf(kam, __shfl_xor_sync(0xffffffffu, kam, o));
    if (lane == 0) wkam[wid] = kam;
    __syncthreads();

    // ---- Cross-warp finalize: c_n = (Σ_w wR[w][n]) / n!
    if (tid < 32) {
        float s = 0.f;
#pragma unroll
        for (int w = 0; w < NWARPS; w++) s += wR[w][tid];
        if (tid < NC) cS[tid] = s * c_invfact[tid];
        else          cM[tid - NC] = s * c_invfact[tid - NC];
    } else if (tid == 32) {
        float a = 0.f;
#pragma unroll
        for (int w = 0; w < NWARPS; w++) a = fmaxf(a, wkam[w]);
        s_kam = a;
    }
    __syncthreads();

    const float kamf = s_kam;
    const float w0h  = W0[h];

    // ---- Row eval straight from retained registers (no reloads).
    float o0 = 0.f, o1 = 0.f, o2 = 0.f, o3 = 0.f;
    if (act) {
        const float u0 = xv.x * qw.x, u1 = xv.y * qw.y, u2 = xv.z * qw.z, u3 = xv.w * qw.w;
        const float umax = fmaxf(fmaxf(fabsf(u0), fabsf(u1)), fmaxf(fabsf(u2), fabsf(u3)));

        if (umax * kamf <= GUARD) {
            float d0 = cS[NC - 1], d1 = d0, d2 = d0, d3 = d0;
            float m0 = cM[NC - 1], m1 = m0, m2 = m0, m3 = m0;
#pragma unroll
            for (int n = NC - 2; n >= 0; n--) {
                const float cs = cS[n], cm = cM[n];
                d0 = fmaf(d0, u0, cs);  m0 = fmaf(m0, u0, cm);
                d1 = fmaf(d1, u1, cs);  m1 = fmaf(m1, u1, cm);
                d2 = fmaf(d2, u2, cs);  m2 = fmaf(m2, u2, cm);
                d3 = fmaf(d3, u3, cs);  m3 = fmaf(m3, u3, cm);
            }
            // diagonal masked post-softmax: subtract exp(u*k_i)*v_i from numerator
            const float e0 = __expf(u0 * k0);
            const float e1 = __expf(u1 * k1);
            const float e2 = __expf(u2 * k2);
            const float e3 = __expf(u3 * k3);
            o0 = __fdividef(m0 - e0 * v0, d0);
            o1 = __fdividef(m1 - e1 * v1, d1);
            o2 = __fdividef(m2 - e2 * v2, d2);
            o3 = __fdividef(m3 - e3 * v3, d3);
        } else {
            const float* xb = x  + b * G_DIM;
            const float* wk = WK + h * G_DIM;
            const float* wv = WV + h * G_DIM;
            const float u0f = xv.x * qw.x, u1f = xv.y * qw.y;
            const float u2f = xv.z * qw.z, u3f = xv.w * qw.w;
            o0 = exact_row(u0f, xb, wk, wv, kamf, k0, v0);
            o1 = exact_row(u1f, xb, wk, wv, kamf, k1, v1);
            o2 = exact_row(u2f, xb, wk, wv, kamf, k2, v2);
            o3 = exact_row(u3f, xb, wk, wv, kamf, k3, v3);
        }
    }

    // ---- Late acquire: all 5 zero-bumps happened microseconds ago; spin ~0.
    if (tid == 0) {
        const unsigned target = s_target;
        volatile unsigned* vz = &g_zero[b];
        while ((int)(*vz - target) < 0) { __nanosleep(32); }
    }
    __syncthreads();
    __threadfence();                 // acquire: zero-stores of all 5 CTAs visible

    if (act) {
        const int i = 4 * tid;
        atomicAdd(ob + i + 0, w0h * o0);
        atomicAdd(ob + i + 1, w0h * o1);
        atomicAdd(ob + i + 2, w0h * o2);
        atomicAdd(ob + i + 3, w0h * o3);
    }
}

extern "C" void kernel_launch(void* const* d_in, const int* in_sizes, int n_in,
                              void* d_out, int out_size) {
    const float* x  = (const float*)d_in[0];
    const float* WQ = (const float*)d_in[1];
    const float* WK = (const float*)d_in[2];
    const float* WV = (const float*)d_in[3];
    const float* W0 = (const float*)d_in[4];
    float* out = (float*)d_out;

    dim3 grid(B_DIM, H_DIM);
    attn_head_red_kernel<<<grid, NTHREADS>>>(x, WQ, WK, WV, W0, out);
}

// round 15
// speedup vs baseline: 1.2294x; 1.2294x over previous
#include <cuda_runtime.h>

#define B_DIM 16
#define G_DIM 1708
#define GV2   (G_DIM / 2)        // 854 <= active threads: one float2 group per thread
#define H_DIM 5
#define NC 16                    // Taylor n = 0..15; 4.5^16/16!/e^4.5 ~ 1.5e-5 at guard
#define GUARD 4.5f
#define NTHREADS 896
#define NWARPS 28

__constant__ float c_invfact[NC] = {
    1.0f, 1.0f, 0.5f,
    1.6666666666666666e-01f, 4.1666666666666664e-02f, 8.3333333333333332e-03f,
    1.3888888888888889e-03f, 1.9841269841269841e-04f, 2.4801587301587302e-05f,
    2.7557319223985893e-06f, 2.7557319223985894e-07f, 2.5052108385441720e-08f,
    2.0876756987868100e-09f, 1.6059043836821616e-10f, 1.1470745597729726e-11f,
    7.6471637318198174e-13f };

// Exact fallback; never taken on this data. Shift m = |u|*kam >= max_j(u*k_j)
// is overflow-safe and cancels in the num/den ratio.
__device__ __noinline__ float exact_row(float u, const float* __restrict__ xb,
                                        const float* __restrict__ wkh,
                                        const float* __restrict__ wvh,
                                        float kam, float ki, float vi) {
    const float m = fabsf(u) * kam;
    float s1 = 0.f, s2 = 0.f;
    for (int j = 0; j < G_DIM; j++) {
        const float xj = xb[j];
        const float kj = xj * wkh[j];
        const float vj = xj * wvh[j];
        const float e  = __expf(fmaf(u, kj, -m));
        s1 += e;
        s2 = fmaf(e, vj, s2);
    }
    const float eii = __expf(fmaf(u, ki, -m));
    return (s2 - eii * vi) / s1;
}

// Shrinking butterfly round: N outputs from 2N inputs across stride S.
// Lane keeps the half whose value-bit matches its own lane-bit S.
template<int S, int N>
__device__ __forceinline__ void red_round(const float* __restrict__ in,
                                          float* __restrict__ outv, int lane) {
    const bool up = (lane & S) != 0;
#pragma unroll
    for (int j = 0; j < N; j++) {
        const float send = up ? in[j] : in[j + N];
        const float recv = __shfl_xor_sync(0xffffffffu, send, S);
        outv[j] = (up ? in[j + N] : in[j]) + recv;
    }
}

// One CTA per (b,h). One float2 group per thread, loaded ONCE and retained in
// registers across moment accumulation, reduction, and row eval.
// den(u) = sum_n (S_n/n!) u^n,  num(u) = sum_n (M_n/n!) u^n
// out[b,i] += W0[h] * (num(q_i) - exp(q_i*k_i)*v_i) / den(q_i)
__global__ __launch_bounds__(NTHREADS, 1)
void attn_head_red_kernel(const float* __restrict__ x,  const float* __restrict__ WQ,
                          const float* __restrict__ WK, const float* __restrict__ WV,
                          const float* __restrict__ W0, float* __restrict__ out) {
    const int b = blockIdx.x;
    const int h = blockIdx.y;
    const int tid = threadIdx.x;
    const int wid = tid >> 5, lane = tid & 31;
    const bool act = (tid < GV2);

    __shared__ float wR[NWARPS][32];        // per-warp reduced (S0..15, M0..15)
    __shared__ float cS[NC], cM[NC];
    __shared__ float wkam[NWARPS];
    __shared__ float s_kam;

    const float2* __restrict__ xb2 = (const float2*)(x  + b * G_DIM);
    const float2* __restrict__ wq2 = (const float2*)(WQ + h * G_DIM);
    const float2* __restrict__ wk2 = (const float2*)(WK + h * G_DIM);
    const float2* __restrict__ wv2 = (const float2*)(WV + h * G_DIM);

    // ---- Load everything this thread will ever need (one DRAM round-trip).
    float2 xv = make_float2(0.f, 0.f), qw = xv, kw = xv, vw = xv;
    if (act) {
        xv = xb2[tid];
        qw = wq2[tid];   // prefetched: latency hides under moments+reduction
        kw = wk2[tid];
        vw = wv2[tid];
    }
    const float k0 = xv.x * kw.x, v0 = xv.x * vw.x;
    const float k1 = xv.y * kw.y, v1 = xv.y * vw.y;

    float kam = fmaxf(fabsf(k0), fabsf(k1));

    // ---- Moments: R[0..15] = S_n partials, R[16..31] = M_n partials.
    float R[32];
#pragma unroll
    for (int n = 0; n < 32; n++) R[n] = 0.f;
    if (act) {
#pragma unroll
        for (int e = 0; e < 2; e++) {
            const float k = (e == 0) ? k0 : k1;
            const float v = (e == 0) ? v0 : v1;
            const float ksq = k * k;
            const float kq  = ksq * ksq;
            float p0 = 1.f, p1 = k, p2 = ksq, p3 = ksq * k;
#pragma unroll
            for (int n = 0; n < NC; n += 4) {
                R[n + 0]      += p0;  R[NC + n + 0] = fmaf(p0, v, R[NC + n + 0]);
                R[n + 1]      += p1;  R[NC + n + 1] = fmaf(p1, v, R[NC + n + 1]);
                R[n + 2]      += p2;  R[NC + n + 2] = fmaf(p2, v, R[NC + n + 2]);
                R[n + 3]      += p3;  R[NC + n + 3] = fmaf(p3, v, R[NC + n + 3]);
                p0 *= kq; p1 *= kq; p2 *= kq; p3 *= kq;
            }
        }
    }

    // ---- Shrinking-butterfly warp reduce: 31 shuffle-pairs total.
    // After 5 rounds, lane l holds the warp-sum of value index l.
    float L16[16], L8[8], L4[4], L2[2], L1[1];
    red_round<16, 16>(R,   L16, lane);
    red_round< 8,  8>(L16, L8,  lane);
    red_round< 4,  4>(L8,  L4,  lane);
    red_round< 2,  2>(L4,  L2,  lane);
    red_round< 1,  1>(L2,  L1,  lane);
    wR[wid][lane] = L1[0];

#pragma unroll
    for (int o = 16; o > 0; o >>= 1)
        kam = fmaxf(kam, __shfl_xor_sync(0xffffffffu, kam, o));
    if (lane == 0) wkam[wid] = kam;
    __syncthreads();

    // ---- Cross-warp finalize: c_n = (Σ_w wR[w][n]) / n!
    if (tid < 32) {
        float s = 0.f;
#pragma unroll
        for (int w = 0; w < NWARPS; w++) s += wR[w][tid];
        if (tid < NC) cS[tid] = s * c_invfact[tid];
        else          cM[tid - NC] = s * c_invfact[tid - NC];
    } else if (tid == 32) {
        float a = 0.f;
#pragma unroll
        for (int w = 0; w < NWARPS; w++) a = fmaxf(a, wkam[w]);
        s_kam = a;
    }
    __syncthreads();

    if (!act) return;

    const float kamf = s_kam;
    const float w0h  = W0[h];
    float* __restrict__ ob = out + b * G_DIM;

    // ---- Row eval straight from retained registers (no reloads).
    const float u0 = xv.x * qw.x, u1 = xv.y * qw.y;
    const float umax = fmaxf(fabsf(u0), fabsf(u1));

    float o0, o1;
    if (umax * kamf <= GUARD) {
        float d0 = cS[NC - 1], d1 = d0;
        float m0 = cM[NC - 1], m1 = m0;
#pragma unroll
        for (int n = NC - 2; n >= 0; n--) {
            const float cs = cS[n], cm = cM[n];
            d0 = fmaf(d0, u0, cs);  m0 = fmaf(m0, u0, cm);
            d1 = fmaf(d1, u1, cs);  m1 = fmaf(m1, u1, cm);
        }
        // diagonal masked post-softmax: subtract exp(u*k_i)*v_i from numerator
        const float e0 = __expf(u0 * k0);
        const float e1 = __expf(u1 * k1);
        o0 = __fdividef(m0 - e0 * v0, d0);
        o1 = __fdividef(m1 - e1 * v1, d1);
    } else {
        const float* xb = x  + b * G_DIM;
        const float* wk = WK + h * G_DIM;
        const float* wv = WV + h * G_DIM;
        o0 = exact_row(u0, xb, wk, wv, kamf, k0, v0);
        o1 = exact_row(u1, xb, wk, wv, kamf, k1, v1);
    }
    const int i = 2 * tid;
    atomicAdd(ob + i + 0, w0h * o0);
    atomicAdd(ob + i + 1, w0h * o1);
}

extern "C" void kernel_launch(void* const* d_in, const int* in_sizes, int n_in,
                              void* d_out, int out_size) {
    const float* x  = (const float*)d_in[0];
    const float* WQ = (const float*)d_in[1];
    const float* WK = (const float*)d_in[2];
    const float* WV = (const float*)d_in[3];
    const float* W0 = (const float*)d_in[4];
    float* out = (float*)d_out;

    // Zero the accumulator (graph-capturable memset node; no allocation).
    cudaMemsetAsync(out, 0, (size_t)out_size * sizeof(float), 0);

    dim3 grid(B_DIM, H_DIM);
    attn_head_red_kernel<<<grid, NTHREADS>>>(x, WQ, WK, WV, W0, out);
}